// round 7
// baseline (speedup 1.0000x reference)
#include <cuda_runtime.h>
#include <cstdint>

// Problem shape (fixed by the reference)
#define BDIM 4096
#define NIN  2048
#define NOUT 2048
#define GS   8
#define KDIM (NIN * GS)   // 16384 contraction length

// 256 MB scratch for the TF32-pre-rounded basis matrix A[b][(i,k)]
__device__ float g_basis[(size_t)BDIM * KDIM];

// ---------------------------------------------------------------------------
// helpers
// ---------------------------------------------------------------------------
__device__ __forceinline__ uint32_t tf32_rna_u(float x) {
    uint32_t u;
    asm("cvt.rna.tf32.f32 %0, %1;" : "=r"(u) : "f"(x));
    return u;
}
__device__ __forceinline__ float tf32_rna_f(float x) {
    return __uint_as_float(tf32_rna_u(x));
}
__device__ __forceinline__ uint32_t smem_u32(const void* p) {
    return (uint32_t)__cvta_generic_to_shared(p);
}
__device__ __forceinline__ void cp_async16(uint32_t s, const void* g) {
    asm volatile("cp.async.cg.shared.global [%0], [%1], 16;\n" :: "r"(s), "l"(g));
}
__device__ __forceinline__ void mma_tf32(float* d, const uint32_t* a, const uint32_t* b) {
    asm volatile(
        "mma.sync.aligned.m16n8k8.row.col.f32.tf32.tf32.f32 "
        "{%0,%1,%2,%3},{%4,%5,%6,%7},{%8,%9},{%0,%1,%2,%3};\n"
        : "+f"(d[0]), "+f"(d[1]), "+f"(d[2]), "+f"(d[3])
        : "r"(a[0]), "r"(a[1]), "r"(a[2]), "r"(a[3]), "r"(b[0]), "r"(b[1]));
}

// ---------------------------------------------------------------------------
// Phase 1: basis[b,i,k] = exp(-5(x-g_k)^2) / (sum_k + 1e-8), rna-rounded to
// TF32 and stored as A[b][i*8+k] (row-major, K contiguous).
// ---------------------------------------------------------------------------
__global__ void basis_kernel(const float* __restrict__ x,
                             const float* __restrict__ grid) {
    int t = blockIdx.x * blockDim.x + threadIdx.x;   // over BDIM*NIN = 8.4M
    if (t >= BDIM * NIN) return;
    float xv = x[t];
    float e[GS];
    float s = 0.f;
#pragma unroll
    for (int k = 0; k < GS; k++) {
        float d = xv - __ldg(grid + k);
        e[k] = __expf(-5.0f * d * d);
        s += e[k];
    }
    float inv = 1.0f / (s + 1e-8f);
    float4 v0, v1;
    v0.x = tf32_rna_f(e[0] * inv);
    v0.y = tf32_rna_f(e[1] * inv);
    v0.z = tf32_rna_f(e[2] * inv);
    v0.w = tf32_rna_f(e[3] * inv);
    v1.x = tf32_rna_f(e[4] * inv);
    v1.y = tf32_rna_f(e[5] * inv);
    v1.z = tf32_rna_f(e[6] * inv);
    v1.w = tf32_rna_f(e[7] * inv);
    float4* p = (float4*)(g_basis + (size_t)t * GS);
    p[0] = v0;
    p[1] = v1;
}

// ---------------------------------------------------------------------------
// Phase 2: out[4096,2048] = A[4096,16384] @ B[16384,2048]
// where B[(i*8+k)][j] = coef[i][j][k]. The B smem stage reads coef directly
// (16B chunks coef[i][j][k..k+4]) -> smem Bs[j][kk], i.e. the layout
// transpose happens for free inside the tile load.
//
// mma.sync.m16n8k8 tf32. CTA tile 128x128x32, 8 warps (4x2), warp tile 32x64,
// 4-stage cp.async pipeline, smem row stride 36 floats (conflict-free frags).
// ---------------------------------------------------------------------------
#define BM 128
#define BN 128
#define BK 32
#define STG 4
#define LDK 36                      // padded smem row stride (floats)
#define GEMM_SMEM (STG * (BM + BN) * LDK * 4)   // 147456 bytes

__global__ __launch_bounds__(256, 1)
void gemm_kernel(const float* __restrict__ coef, float* __restrict__ out) {
    extern __shared__ float sm[];
    float* As = sm;                          // STG * BM * LDK
    float* Bs = sm + STG * BM * LDK;         // STG * BN * LDK

    const int tid  = threadIdx.x;
    const int lane = tid & 31;
    const int wid  = tid >> 5;
    const int m0 = blockIdx.y * BM;
    const int n0 = blockIdx.x * BN;
    const int wm0 = (wid >> 1) * 32;         // 4 warps along M
    const int wn0 = (wid & 1) * 64;          // 2 warps along N
    const int lr = lane >> 2;                // 0..7
    const int lc = lane & 3;                 // 0..3

    const float* A = g_basis;

    auto loadA = [&](int stage, int k0) {
#pragma unroll
        for (int it = 0; it < 4; it++) {
            int idx = tid + it * 256;        // 1024 chunks: 128 rows x 8 float4
            int row = idx >> 3, c4 = idx & 7;
            const float* g = A + (size_t)(m0 + row) * KDIM + k0 + c4 * 4;
            cp_async16(smem_u32(As + stage * BM * LDK + row * LDK + c4 * 4), g);
        }
    };
    auto loadB = [&](int stage, int k0) {
        int i0 = k0 >> 3;                    // k0 multiple of 32 -> i0 multiple of 4
#pragma unroll
        for (int it = 0; it < 4; it++) {
            int idx = tid + it * 256;        // 1024 chunks: 128 j x 8 float4
            int j = idx & 127, c4 = idx >> 7;
            int irel = c4 >> 1, kh = (c4 & 1) * 4;
            const float* g = coef + (size_t)(i0 + irel) * (NOUT * GS)
                                  + (size_t)(n0 + j) * GS + kh;
            cp_async16(smem_u32(Bs + stage * BN * LDK + j * LDK + c4 * 4), g);
        }
    };

    float acc[2][8][4];
#pragma unroll
    for (int mt = 0; mt < 2; mt++)
#pragma unroll
        for (int nt = 0; nt < 8; nt++)
#pragma unroll
            for (int r = 0; r < 4; r++) acc[mt][nt][r] = 0.f;

    const int KT = KDIM / BK;                // 512

    // prologue: fill STG-1 stages
#pragma unroll
    for (int s = 0; s < STG - 1; s++) {
        loadA(s, s * BK);
        loadB(s, s * BK);
        asm volatile("cp.async.commit_group;\n");
    }

    for (int kt = 0; kt < KT; kt++) {
        asm volatile("cp.async.wait_group %0;\n" :: "n"(STG - 2));
        __syncthreads();

        // prefetch stage kt+STG-1 into the slot consumed at iteration kt-1
        int ktn = kt + STG - 1;
        if (ktn < KT) {
            int sl = ktn % STG;
            loadA(sl, ktn * BK);
            loadB(sl, ktn * BK);
        }
        asm volatile("cp.async.commit_group;\n");

        const float* As_ = As + (kt % STG) * BM * LDK;
        const float* Bs_ = Bs + (kt % STG) * BN * LDK;

#pragma unroll
        for (int k8 = 0; k8 < BK; k8 += 8) {
            uint32_t af[2][4];
#pragma unroll
            for (int mt = 0; mt < 2; mt++) {
                int r = wm0 + mt * 16 + lr;
                af[mt][0] = __float_as_uint(As_[r * LDK + k8 + lc]);         // already tf32
                af[mt][1] = __float_as_uint(As_[(r + 8) * LDK + k8 + lc]);
                af[mt][2] = __float_as_uint(As_[r * LDK + k8 + lc + 4]);
                af[mt][3] = __float_as_uint(As_[(r + 8) * LDK + k8 + lc + 4]);
            }
            uint32_t bf[8][2];
#pragma unroll
            for (int nt = 0; nt < 8; nt++) {
                int n = wn0 + nt * 8 + lr;
                bf[nt][0] = tf32_rna_u(Bs_[n * LDK + k8 + lc]);              // rna-round coef
                bf[nt][1] = tf32_rna_u(Bs_[n * LDK + k8 + lc + 4]);
            }
#pragma unroll
            for (int mt = 0; mt < 2; mt++)
#pragma unroll
                for (int nt = 0; nt < 8; nt++)
                    mma_tf32(acc[mt][nt], af[mt], bf[nt]);
        }
    }

    // epilogue: fp32 stores, float2 per mma-tile half
#pragma unroll
    for (int mt = 0; mt < 2; mt++) {
#pragma unroll
        for (int nt = 0; nt < 8; nt++) {
            int r = m0 + wm0 + mt * 16 + lr;
            int c = n0 + wn0 + nt * 8 + lc * 2;
            float2 lo = make_float2(acc[mt][nt][0], acc[mt][nt][1]);
            float2 hi = make_float2(acc[mt][nt][2], acc[mt][nt][3]);
            *(float2*)(out + (size_t)r * NOUT + c) = lo;
            *(float2*)(out + (size_t)(r + 8) * NOUT + c) = hi;
        }
    }
}

// ---------------------------------------------------------------------------
// launch
// ---------------------------------------------------------------------------
extern "C" void kernel_launch(void* const* d_in, const int* in_sizes, int n_in,
                              void* d_out, int out_size) {
    const float* x    = (const float*)d_in[0];   // [4096, 2048]
    const float* coef = (const float*)d_in[1];   // [2048, 2048, 8]
    const float* grid = (const float*)d_in[2];   // [8]
    float* out = (float*)d_out;                  // [4096, 2048]

    (void)in_sizes; (void)n_in; (void)out_size;

    // Phase 1: basis -> g_basis (TF32 pre-rounded)
    basis_kernel<<<(BDIM * NIN) / 256, 256>>>(x, grid);

    // Phase 2: tensor-core GEMM
    cudaFuncSetAttribute(gemm_kernel,
                         cudaFuncAttributeMaxDynamicSharedMemorySize, GEMM_SMEM);
    dim3 g(NOUT / BN, BDIM / BM);                // (16, 32)
    gemm_kernel<<<g, 256, GEMM_SMEM>>>(coef, out);
}

// round 9
// speedup vs baseline: 1.7813x; 1.7813x over previous
#include <cuda_runtime.h>
#include <cstdint>

// Problem shape (fixed by the reference)
#define BDIM 4096
#define NIN  2048
#define NOUT 2048
#define GS   8
#define KDIM (NIN * GS)   // 16384 contraction length

// Scratch: TF32-pre-rounded basis A[b][(i*8+k)] (256 MB) and coef (128 MB)
__device__ float g_basis[(size_t)BDIM * KDIM];
__device__ float g_coef[(size_t)NIN * NOUT * GS];

// ---------------------------------------------------------------------------
// helpers
// ---------------------------------------------------------------------------
__device__ __forceinline__ uint32_t tf32_rna_u(float x) {
    uint32_t u;
    asm("cvt.rna.tf32.f32 %0, %1;" : "=r"(u) : "f"(x));
    return u;
}
__device__ __forceinline__ float tf32_rna_f(float x) {
    return __uint_as_float(tf32_rna_u(x));
}
__device__ __forceinline__ uint32_t smem_u32(const void* p) {
    return (uint32_t)__cvta_generic_to_shared(p);
}
__device__ __forceinline__ void cp_async16(uint32_t s, const void* g) {
    asm volatile("cp.async.cg.shared.global [%0], [%1], 16;\n" :: "r"(s), "l"(g));
}
__device__ __forceinline__ void mma_tf32(float* d, const uint32_t* a, const uint32_t* b) {
    asm volatile(
        "mma.sync.aligned.m16n8k8.row.col.f32.tf32.tf32.f32 "
        "{%0,%1,%2,%3},{%4,%5,%6,%7},{%8,%9},{%0,%1,%2,%3};\n"
        : "+f"(d[0]), "+f"(d[1]), "+f"(d[2]), "+f"(d[3])
        : "r"(a[0]), "r"(a[1]), "r"(a[2]), "r"(a[3]), "r"(b[0]), "r"(b[1]));
}

// ---------------------------------------------------------------------------
// Phase 1a: basis[b,i,k] = exp(-5(x-g_k)^2)/(sum+1e-8), rna->TF32,
// stored as A[b][i*8+k] row-major (K contiguous).
// ---------------------------------------------------------------------------
__global__ void basis_kernel(const float* __restrict__ x,
                             const float* __restrict__ grid) {
    int t = blockIdx.x * blockDim.x + threadIdx.x;
    if (t >= BDIM * NIN) return;
    float xv = x[t];
    float e[GS];
    float s = 0.f;
#pragma unroll
    for (int k = 0; k < GS; k++) {
        float d = xv - __ldg(grid + k);
        e[k] = __expf(-5.0f * d * d);
        s += e[k];
    }
    float inv = 1.0f / (s + 1e-8f);
    float4 v0, v1;
    v0.x = tf32_rna_f(e[0] * inv); v0.y = tf32_rna_f(e[1] * inv);
    v0.z = tf32_rna_f(e[2] * inv); v0.w = tf32_rna_f(e[3] * inv);
    v1.x = tf32_rna_f(e[4] * inv); v1.y = tf32_rna_f(e[5] * inv);
    v1.z = tf32_rna_f(e[6] * inv); v1.w = tf32_rna_f(e[7] * inv);
    float4* p = (float4*)(g_basis + (size_t)t * GS);
    p[0] = v0;
    p[1] = v1;
}

// ---------------------------------------------------------------------------
// Phase 1b: pre-round coef to TF32 (hoists the per-fragment cvt out of the
// GEMM mainloop; numerically identical to rounding in-loop).
// ---------------------------------------------------------------------------
__global__ void coef_round_kernel(const float* __restrict__ coef) {
    int t = blockIdx.x * blockDim.x + threadIdx.x;   // over 33.5M/4 float4s
    if (t >= (NIN * NOUT * GS) / 4) return;
    float4 v = ((const float4*)coef)[t];
    v.x = tf32_rna_f(v.x);
    v.y = tf32_rna_f(v.y);
    v.z = tf32_rna_f(v.z);
    v.w = tf32_rna_f(v.w);
    ((float4*)g_coef)[t] = v;
}

// ---------------------------------------------------------------------------
// Phase 2: out[4096,2048] = A[4096,16384] @ B[16384,2048]
// where B[(i*8+k)][j] = coef[i][j][k]; B smem stage transposes for free.
//
// mma.sync.m16n8k8 tf32. CTA tile 128x128x32, 8 warps (4x2), warp tile 32x64,
// 3-stage cp.async pipeline (smem 110.6 KB -> 2 CTAs/SM, 16 warps/SM),
// smem row stride 36 floats (conflict-free fragment loads).
// ---------------------------------------------------------------------------
#define BM 128
#define BN 128
#define BK 32
#define STG 3
#define LDK 36                      // padded smem row stride (floats)
#define GEMM_SMEM (STG * (BM + BN) * LDK * 4)   // 110592 bytes

__global__ __launch_bounds__(256, 2)
void gemm_kernel(float* __restrict__ out) {
    extern __shared__ float sm[];
    float* As = sm;                          // STG * BM * LDK
    float* Bs = sm + STG * BM * LDK;         // STG * BN * LDK

    const int tid  = threadIdx.x;
    const int lane = tid & 31;
    const int wid  = tid >> 5;
    const int m0 = blockIdx.y * BM;
    const int n0 = blockIdx.x * BN;
    const int wm0 = (wid >> 1) * 32;         // 4 warps along M
    const int wn0 = (wid & 1) * 64;          // 2 warps along N
    const int lr = lane >> 2;                // 0..7
    const int lc = lane & 3;                 // 0..3

    auto loadA = [&](int stage, int k0) {
#pragma unroll
        for (int it = 0; it < 4; it++) {
            int idx = tid + it * 256;        // 1024 chunks: 128 rows x 8 float4
            int row = idx >> 3, c4 = idx & 7;
            const float* g = g_basis + (size_t)(m0 + row) * KDIM + k0 + c4 * 4;
            cp_async16(smem_u32(As + stage * BM * LDK + row * LDK + c4 * 4), g);
        }
    };
    auto loadB = [&](int stage, int k0) {
        int i0 = k0 >> 3;                    // k0 multiple of 32 -> i0 multiple of 4
#pragma unroll
        for (int it = 0; it < 4; it++) {
            int idx = tid + it * 256;        // 1024 chunks: 128 j x 8 float4
            int j = idx & 127, c4 = idx >> 7;
            int irel = c4 >> 1, kh = (c4 & 1) * 4;
            const float* g = g_coef + (size_t)(i0 + irel) * (NOUT * GS)
                                    + (size_t)(n0 + j) * GS + kh;
            cp_async16(smem_u32(Bs + stage * BN * LDK + j * LDK + c4 * 4), g);
        }
    };

    float acc[2][8][4];
#pragma unroll
    for (int mt = 0; mt < 2; mt++)
#pragma unroll
        for (int nt = 0; nt < 8; nt++)
#pragma unroll
            for (int r = 0; r < 4; r++) acc[mt][nt][r] = 0.f;

    const int KT = KDIM / BK;                // 512

    // prologue: fill STG-1 stages
#pragma unroll
    for (int s = 0; s < STG - 1; s++) {
        loadA(s, s * BK);
        loadB(s, s * BK);
        asm volatile("cp.async.commit_group;\n");
    }

    for (int kt = 0; kt < KT; kt++) {
        asm volatile("cp.async.wait_group %0;\n" :: "n"(STG - 2));
        __syncthreads();

        // prefetch stage kt+STG-1 into the slot consumed at iteration kt-1
        int ktn = kt + STG - 1;
        if (ktn < KT) {
            int sl = ktn % STG;
            loadA(sl, ktn * BK);
            loadB(sl, ktn * BK);
        }
        asm volatile("cp.async.commit_group;\n");

        const float* As_ = As + (kt % STG) * BM * LDK;
        const float* Bs_ = Bs + (kt % STG) * BN * LDK;

#pragma unroll
        for (int k8 = 0; k8 < BK; k8 += 8) {
            uint32_t af[2][4];
#pragma unroll
            for (int mt = 0; mt < 2; mt++) {
                int r = wm0 + mt * 16 + lr;
                af[mt][0] = __float_as_uint(As_[r * LDK + k8 + lc]);       // pre-rounded tf32
                af[mt][1] = __float_as_uint(As_[(r + 8) * LDK + k8 + lc]);
                af[mt][2] = __float_as_uint(As_[r * LDK + k8 + lc + 4]);
                af[mt][3] = __float_as_uint(As_[(r + 8) * LDK + k8 + lc + 4]);
            }
            uint32_t bf[8][2];
#pragma unroll
            for (int nt = 0; nt < 8; nt++) {
                int n = wn0 + nt * 8 + lr;
                bf[nt][0] = __float_as_uint(Bs_[n * LDK + k8 + lc]);       // pre-rounded tf32
                bf[nt][1] = __float_as_uint(Bs_[n * LDK + k8 + lc + 4]);
            }
#pragma unroll
            for (int mt = 0; mt < 2; mt++)
#pragma unroll
                for (int nt = 0; nt < 8; nt++)
                    mma_tf32(acc[mt][nt], af[mt], bf[nt]);
        }
    }

    // epilogue: fp32 stores, float2 per mma-tile half
#pragma unroll
    for (int mt = 0; mt < 2; mt++) {
#pragma unroll
        for (int nt = 0; nt < 8; nt++) {
            int r = m0 + wm0 + mt * 16 + lr;
            int c = n0 + wn0 + nt * 8 + lc * 2;
            float2 lo = make_float2(acc[mt][nt][0], acc[mt][nt][1]);
            float2 hi = make_float2(acc[mt][nt][2], acc[mt][nt][3]);
            *(float2*)(out + (size_t)r * NOUT + c) = lo;
            *(float2*)(out + (size_t)(r + 8) * NOUT + c) = hi;
        }
    }
}

// ---------------------------------------------------------------------------
// launch
// ---------------------------------------------------------------------------
extern "C" void kernel_launch(void* const* d_in, const int* in_sizes, int n_in,
                              void* d_out, int out_size) {
    const float* x    = (const float*)d_in[0];   // [4096, 2048]
    const float* coef = (const float*)d_in[1];   // [2048, 2048, 8]
    const float* grid = (const float*)d_in[2];   // [8]
    float* out = (float*)d_out;                  // [4096, 2048]
    (void)in_sizes; (void)n_in; (void)out_size;

    // Phase 1: basis -> g_basis, coef -> g_coef (both TF32 pre-rounded)
    basis_kernel<<<(BDIM * NIN) / 256, 256>>>(x, grid);
    coef_round_kernel<<<(NIN * NOUT * GS / 4) / 256, 256>>>(coef);

    // Phase 2: tensor-core GEMM (2 CTAs/SM)
    cudaFuncSetAttribute(gemm_kernel,
                         cudaFuncAttributeMaxDynamicSharedMemorySize, GEMM_SMEM);
    dim3 g(NOUT / BN, BDIM / BM);                // (16, 32) = 512 CTAs
    gemm_kernel<<<g, 256, GEMM_SMEM>>>(out);
}

// round 10
// speedup vs baseline: 2.2551x; 1.2660x over previous
#include <cuda_runtime.h>
#include <cstdint>

// Problem shape (fixed by the reference)
#define BDIM 4096
#define NIN  2048
#define NOUT 2048
#define GS   8
#define KDIM (NIN * GS)     // 16384 contraction length
#define NBLK (KDIM / 32)    // 512 K-blocks of 32

// Scratch (TF32 pre-rounded, K-permuted within each 32-block):
//   g_basis[b][blk*32 + p]         : A, 256 MB
//   g_coefT[blk][j][p] (32 floats) : B transposed, 128 MB
__device__ float g_basis[(size_t)BDIM * KDIM];
__device__ float g_coefT[(size_t)NBLK * NOUT * 32];

// ---------------------------------------------------------------------------
// helpers
// ---------------------------------------------------------------------------
__device__ __forceinline__ uint32_t tf32_rna_u(float x) {
    uint32_t u;
    asm("cvt.rna.tf32.f32 %0, %1;" : "=r"(u) : "f"(x));
    return u;
}
__device__ __forceinline__ float tf32_rna_f(float x) {
    return __uint_as_float(tf32_rna_u(x));
}
__device__ __forceinline__ uint32_t smem_u32(const void* p) {
    return (uint32_t)__cvta_generic_to_shared(p);
}
__device__ __forceinline__ void cp_async16(uint32_t s, const void* g) {
    asm volatile("cp.async.cg.shared.global [%0], [%1], 16;\n" :: "r"(s), "l"(g));
}
__device__ __forceinline__ void mma_tf32(float* d, const uint32_t* a, const uint32_t* b) {
    asm volatile(
        "mma.sync.aligned.m16n8k8.row.col.f32.tf32.tf32.f32 "
        "{%0,%1,%2,%3},{%4,%5,%6,%7},{%8,%9},{%0,%1,%2,%3};\n"
        : "+f"(d[0]), "+f"(d[1]), "+f"(d[2]), "+f"(d[3])
        : "r"(a[0]), "r"(a[1]), "r"(a[2]), "r"(a[3]), "r"(b[0]), "r"(b[1]));
}

// K-permutation within a 32-block: virtual (g, u), g = i_rel 0..3, u = k 0..7:
//   p(g,u) = 16*(g>>1) + 4*(u&3) + 2*(g&1) + (u>>2)
// => 16B chunk L = (u&3) + 4*(g>>1) holds [g_even:k_lo, g_even:k_hi, g_odd:k_lo, g_odd:k_hi]
// XOR swizzle of chunk position within smem row r (conflict-free LDS.128):
__device__ __forceinline__ int pchunk(int L, int r) {
    return ((L & 3) ^ ((r >> 1) & 3)) + (((L >> 2) + r) & 1) * 4;
}

// ---------------------------------------------------------------------------
// Phase 1a: basis -> g_basis, TF32-rounded, K-permuted.
// Thread t owns (b,i) = row block (t>>2), group g = t&3; writes 4 float2
// (e_c, e_{c+4}) at p = 16*(g>>1) + 4c + 2*(g&1).
// ---------------------------------------------------------------------------
__global__ void basis_kernel(const float* __restrict__ x,
                             const float* __restrict__ grid) {
    int t = blockIdx.x * blockDim.x + threadIdx.x;
    if (t >= BDIM * NIN) return;
    float xv = x[t];
    float e[GS];
    float s = 0.f;
#pragma unroll
    for (int k = 0; k < GS; k++) {
        float d = xv - __ldg(grid + k);
        e[k] = __expf(-5.0f * d * d);
        s += e[k];
    }
    float inv = 1.0f / (s + 1e-8f);
    int g = t & 3;
    float* base = g_basis + (size_t)(t >> 2) * 32 + 16 * (g >> 1) + 2 * (g & 1);
#pragma unroll
    for (int c = 0; c < 4; c++) {
        float2 v = make_float2(tf32_rna_f(e[c] * inv), tf32_rna_f(e[c + 4] * inv));
        *(float2*)(base + 4 * c) = v;
    }
}

// ---------------------------------------------------------------------------
// Phase 1b: coef -> g_coefT[blk][j][32], TF32-rounded, K-permuted.
// Thread owns (blk, j): reads coef[4blk+di][j][0..7] (di=0..3), writes one
// permuted 128B row as 8 float4 chunks.
// ---------------------------------------------------------------------------
__global__ void coefT_kernel(const float* __restrict__ coef) {
    int idx = blockIdx.x * blockDim.x + threadIdx.x;
    if (idx >= NBLK * NOUT) return;
    int blk = idx >> 11, j = idx & (NOUT - 1);
    float v[4][8];
#pragma unroll
    for (int di = 0; di < 4; di++) {
        const float4* s =
            (const float4*)(coef + ((size_t)(blk * 4 + di) * NOUT + j) * GS);
        float4 lo = s[0], hi = s[1];
        v[di][0] = lo.x; v[di][1] = lo.y; v[di][2] = lo.z; v[di][3] = lo.w;
        v[di][4] = hi.x; v[di][5] = hi.y; v[di][6] = hi.z; v[di][7] = hi.w;
    }
    float4* dst = (float4*)(g_coefT + (size_t)idx * 32);
#pragma unroll
    for (int L = 0; L < 8; L++) {
        int h = L >> 2, c = L & 3;
        float4 o;
        o.x = tf32_rna_f(v[2 * h][c]);
        o.y = tf32_rna_f(v[2 * h][c + 4]);
        o.z = tf32_rna_f(v[2 * h + 1][c]);
        o.w = tf32_rna_f(v[2 * h + 1][c + 4]);
        dst[L] = o;
    }
}

// ---------------------------------------------------------------------------
// Phase 2: out = A @ B. CTA 128x128x32, 8 warps (4x2), warp 32x64,
// 3-stage cp.async pipeline, 96 KB smem -> 2 CTAs/SM.
// All fragment loads are LDS.128 (K-permuted + XOR-swizzled rows).
// ---------------------------------------------------------------------------
#define BM 128
#define BN 128
#define STG 3
#define AB  (128 * 128)        // 16 KB per A tile
#define STB (2 * AB)           // 32 KB per stage
#define GEMM_SMEM (STG * STB)  // 98304 bytes
#define KT NBLK                // 512 iterations

__global__ __launch_bounds__(256, 2)
void gemm_kernel(float* __restrict__ out) {
    extern __shared__ __align__(128) char smem[];

    const int tid  = threadIdx.x;
    const int lane = tid & 31;
    const int wid  = tid >> 5;
    const int m0 = blockIdx.y * BM;
    const int n0 = blockIdx.x * BN;
    const int wm0 = (wid >> 1) * 32;     // 4 warps along M
    const int wn0 = (wid & 1) * 64;      // 2 warps along N
    const int lr = lane >> 2;            // groupID 0..7
    const int lc = lane & 3;             // threadID-in-group 0..3

    auto loadA = [&](int stage, int kt_) {
        char* base = smem + stage * STB;
#pragma unroll
        for (int it = 0; it < 4; it++) {
            int idx = tid + it * 256;        // 1024 chunks: 128 rows x 8
            int row = idx >> 3, L = idx & 7;
            const float* g = g_basis + (size_t)(m0 + row) * KDIM + kt_ * 32 + L * 4;
            cp_async16(smem_u32(base + row * 128 + pchunk(L, row) * 16), g);
        }
    };
    auto loadB = [&](int stage, int kt_) {
        char* base = smem + stage * STB + AB;
#pragma unroll
        for (int it = 0; it < 4; it++) {
            int idx = tid + it * 256;        // 1024 chunks: 128 j x 8
            int j = idx >> 3, L = idx & 7;
            const float* g = g_coefT + ((size_t)kt_ * NOUT + n0 + j) * 32 + L * 4;
            cp_async16(smem_u32(base + j * 128 + pchunk(L, j) * 16), g);
        }
    };

    // per-thread fragment offsets (h=0; h=1 is XOR 64)
    int aoff[2], boff[8];
#pragma unroll
    for (int mt = 0; mt < 2; mt++) {
        int r = wm0 + mt * 16 + lr;
        aoff[mt] = r * 128 + (((lc ^ ((r >> 1) & 3)) + (r & 1) * 4) * 16);
    }
#pragma unroll
    for (int nt = 0; nt < 8; nt++) {
        int n = wn0 + nt * 8 + lr;
        boff[nt] = n * 128 + (((lc ^ ((n >> 1) & 3)) + (n & 1) * 4) * 16);
    }

    float acc[2][8][4];
#pragma unroll
    for (int mt = 0; mt < 2; mt++)
#pragma unroll
        for (int nt = 0; nt < 8; nt++)
#pragma unroll
            for (int r = 0; r < 4; r++) acc[mt][nt][r] = 0.f;

    // prologue
    loadA(0, 0); loadB(0, 0);
    asm volatile("cp.async.commit_group;\n");
    loadA(1, 1); loadB(1, 1);
    asm volatile("cp.async.commit_group;\n");

    for (int kt = 0; kt < KT; kt++) {
        asm volatile("cp.async.wait_group 1;\n");
        __syncthreads();

        int ktn = kt + STG - 1;
        if (ktn < KT) {
            loadA(ktn % STG, ktn);
            loadB(ktn % STG, ktn);
        }
        asm volatile("cp.async.commit_group;\n");

        const char* As_ = smem + (kt % STG) * STB;
        const char* Bs_ = As_ + AB;

#pragma unroll
        for (int h = 0; h < 2; h++) {            // chunk-pair (groups 2h, 2h+1)
            const int hx = h * 64;
            float4 a[2][2];
#pragma unroll
            for (int mt = 0; mt < 2; mt++) {
                a[mt][0] = *(const float4*)(As_ + (aoff[mt] ^ hx));          // row r
                a[mt][1] = *(const float4*)(As_ + ((aoff[mt] ^ hx) + 1024)); // row r+8
            }
#pragma unroll
            for (int half = 0; half < 2; half++) {
                float4 b[4];
#pragma unroll
                for (int q = 0; q < 4; q++)
                    b[q] = *(const float4*)(Bs_ + (boff[half * 4 + q] ^ hx));
#pragma unroll
                for (int mt = 0; mt < 2; mt++) {
#pragma unroll
                    for (int q = 0; q < 4; q++) {
                        int nt = half * 4 + q;
                        // group 2h (even): .x/.y lanes of the chunk
                        uint32_t af0[4] = {
                            __float_as_uint(a[mt][0].x), __float_as_uint(a[mt][1].x),
                            __float_as_uint(a[mt][0].y), __float_as_uint(a[mt][1].y)};
                        uint32_t bf0[2] = {__float_as_uint(b[q].x),
                                           __float_as_uint(b[q].y)};
                        mma_tf32(acc[mt][nt], af0, bf0);
                        // group 2h+1 (odd): .z/.w lanes
                        uint32_t af1[4] = {
                            __float_as_uint(a[mt][0].z), __float_as_uint(a[mt][1].z),
                            __float_as_uint(a[mt][0].w), __float_as_uint(a[mt][1].w)};
                        uint32_t bf1[2] = {__float_as_uint(b[q].z),
                                           __float_as_uint(b[q].w)};
                        mma_tf32(acc[mt][nt], af1, bf1);
                    }
                }
            }
        }
    }

    // epilogue: fp32 stores
#pragma unroll
    for (int mt = 0; mt < 2; mt++) {
#pragma unroll
        for (int nt = 0; nt < 8; nt++) {
            int r = m0 + wm0 + mt * 16 + lr;
            int c = n0 + wn0 + nt * 8 + lc * 2;
            float2 lo = make_float2(acc[mt][nt][0], acc[mt][nt][1]);
            float2 hi = make_float2(acc[mt][nt][2], acc[mt][nt][3]);
            *(float2*)(out + (size_t)r * NOUT + c) = lo;
            *(float2*)(out + (size_t)(r + 8) * NOUT + c) = hi;
        }
    }
}

// ---------------------------------------------------------------------------
// launch
// ---------------------------------------------------------------------------
extern "C" void kernel_launch(void* const* d_in, const int* in_sizes, int n_in,
                              void* d_out, int out_size) {
    const float* x    = (const float*)d_in[0];   // [4096, 2048]
    const float* coef = (const float*)d_in[1];   // [2048, 2048, 8]
    const float* grid = (const float*)d_in[2];   // [8]
    float* out = (float*)d_out;                  // [4096, 2048]
    (void)in_sizes; (void)n_in; (void)out_size;

    basis_kernel<<<(BDIM * NIN) / 256, 256>>>(x, grid);
    coefT_kernel<<<(NBLK * NOUT) / 256, 256>>>(coef);

    cudaFuncSetAttribute(gemm_kernel,
                         cudaFuncAttributeMaxDynamicSharedMemorySize, GEMM_SMEM);
    dim3 g(NOUT / BN, BDIM / BM);                // (16, 32) = 512 CTAs
    gemm_kernel<<<g, 256, GEMM_SMEM>>>(out);
}

// round 11
// speedup vs baseline: 4.6661x; 2.0691x over previous
#include <cuda_runtime.h>
#include <cuda_fp16.h>
#include <cstdint>

// Problem shape (fixed by the reference)
#define BDIM 4096
#define NIN  2048
#define NOUT 2048
#define GS   8
#define KDIM (NIN * GS)     // 16384 contraction length
#define NBLK (KDIM / 32)    // 512 K-blocks of 32

// fp16 scratch, K-permuted within each 32-block:
//   value (g = i&3, k = 0..7) lives at byte (k>>1)*16 + (g>>1)*8 + (g&1)*4 + (k&1)*2
//   of the 64B block-row. One LDS.128 = a full m16n8k16 fragment (both k-steps).
// g_basisH[b][blk][64B] (128 MB), g_coefTH[blk][j][64B] (64 MB)
__device__ __half g_basisH[(size_t)BDIM * KDIM];
__device__ __half g_coefTH[(size_t)NBLK * NOUT * 32];

// ---------------------------------------------------------------------------
// helpers
// ---------------------------------------------------------------------------
__device__ __forceinline__ uint32_t smem_u32(const void* p) {
    return (uint32_t)__cvta_generic_to_shared(p);
}
__device__ __forceinline__ void cp_async16(uint32_t s, const void* g) {
    asm volatile("cp.async.cg.shared.global [%0], [%1], 16;\n" :: "r"(s), "l"(g));
}
__device__ __forceinline__ void mma_fp16(float* d, uint32_t a0, uint32_t a1,
                                         uint32_t a2, uint32_t a3,
                                         uint32_t b0, uint32_t b1) {
    asm volatile(
        "mma.sync.aligned.m16n8k16.row.col.f32.f16.f16.f32 "
        "{%0,%1,%2,%3},{%4,%5,%6,%7},{%8,%9},{%0,%1,%2,%3};\n"
        : "+f"(d[0]), "+f"(d[1]), "+f"(d[2]), "+f"(d[3])
        : "r"(a0), "r"(a1), "r"(a2), "r"(a3), "r"(b0), "r"(b1));
}
__device__ __forceinline__ uint32_t h2u(__half2 h) {
    return *(uint32_t*)&h;
}

// ---------------------------------------------------------------------------
// Phase 1a: basis -> g_basisH (fp16, K-permuted).
// Thread t owns (b,i): row = t>>2 (= b*512+blk), g = t&3.
// Writes 4 half2 pairs (k=2c, 2c+1) at byte c*16 + (g>>1)*8 + (g&1)*4.
// ---------------------------------------------------------------------------
__global__ void basis_kernel(const float* __restrict__ x,
                             const float* __restrict__ grid) {
    int t = blockIdx.x * blockDim.x + threadIdx.x;
    if (t >= BDIM * NIN) return;
    float xv = x[t];
    float e[GS];
    float s = 0.f;
#pragma unroll
    for (int k = 0; k < GS; k++) {
        float d = xv - __ldg(grid + k);
        e[k] = __expf(-5.0f * d * d);
        s += e[k];
    }
    float inv = 1.0f / (s + 1e-8f);
    int g = t & 3;
    char* base = (char*)g_basisH + (size_t)(t >> 2) * 64 + (g >> 1) * 8 + (g & 1) * 4;
#pragma unroll
    for (int c = 0; c < 4; c++) {
        __half2 v = __floats2half2_rn(e[2 * c] * inv, e[2 * c + 1] * inv);
        *(__half2*)(base + c * 16) = v;
    }
}

// ---------------------------------------------------------------------------
// Phase 1b: coef -> g_coefTH[blk][j][64B] (fp16, K-permuted, transposed).
// Thread owns (blk, j): reads coef[4blk+g][j][0..7], writes one 64B row.
// ---------------------------------------------------------------------------
__global__ void coefT_kernel(const float* __restrict__ coef) {
    int idx = blockIdx.x * blockDim.x + threadIdx.x;
    if (idx >= NBLK * NOUT) return;
    int blk = idx >> 11, j = idx & (NOUT - 1);
    float v[4][8];
#pragma unroll
    for (int g = 0; g < 4; g++) {
        const float4* s =
            (const float4*)(coef + ((size_t)(blk * 4 + g) * NOUT + j) * GS);
        float4 lo = s[0], hi = s[1];
        v[g][0] = lo.x; v[g][1] = lo.y; v[g][2] = lo.z; v[g][3] = lo.w;
        v[g][4] = hi.x; v[g][5] = hi.y; v[g][6] = hi.z; v[g][7] = hi.w;
    }
    uint4* dst = (uint4*)((char*)g_coefTH + (size_t)idx * 64);
#pragma unroll
    for (int c = 0; c < 4; c++) {          // chunk c: k-pair (2c, 2c+1)
        uint4 o;
        o.x = h2u(__floats2half2_rn(v[0][2 * c], v[0][2 * c + 1]));  // s0, g even
        o.y = h2u(__floats2half2_rn(v[1][2 * c], v[1][2 * c + 1]));  // s0, g odd
        o.z = h2u(__floats2half2_rn(v[2][2 * c], v[2][2 * c + 1]));  // s1, g even
        o.w = h2u(__floats2half2_rn(v[3][2 * c], v[3][2 * c + 1]));  // s1, g odd
        dst[c] = o;
    }
}

// ---------------------------------------------------------------------------
// Phase 2: out = A @ B, fp16 HMMA m16n8k16 with fp32 accum.
// CTA 128x128x32, 8 warps (4x2), warp 32x64, 4-stage cp.async pipeline.
// Tiles: 128 rows x 64B, fully linear smem (warp fragment load = 512B
// contiguous -> conflict-free, no swizzle). Stage 16 KB, 64 KB total,
// 2 CTAs/SM.
// ---------------------------------------------------------------------------
#define BM 128
#define BN 128
#define STG 4
#define AB  (128 * 64)         // 8 KB per tile
#define STB (2 * AB)           // 16 KB per stage
#define GEMM_SMEM (STG * STB)  // 65536 bytes
#define KT NBLK                // 512 iterations

__global__ __launch_bounds__(256, 2)
void gemm_kernel(float* __restrict__ out) {
    extern __shared__ __align__(128) char smem[];

    const int tid  = threadIdx.x;
    const int lane = tid & 31;
    const int wid  = tid >> 5;
    const int m0 = blockIdx.y * BM;
    const int n0 = blockIdx.x * BN;
    const int wm0 = (wid >> 1) * 32;     // 4 warps along M
    const int wn0 = (wid & 1) * 64;      // 2 warps along N
    const int lr = lane >> 2;            // 0..7
    const int lc = lane & 3;             // 0..3

    auto loadA = [&](int stage, int kt_) {
        char* base = smem + stage * STB;
#pragma unroll
        for (int it = 0; it < 2; it++) {
            int idx = tid + it * 256;        // 512 chunks: 128 rows x 4
            int row = idx >> 2, L = idx & 3;
            const char* g = (char*)g_basisH
                + ((size_t)(m0 + row) * NBLK + kt_) * 64 + L * 16;
            cp_async16(smem_u32(base + row * 64 + L * 16), g);
        }
    };
    auto loadB = [&](int stage, int kt_) {
        char* base = smem + stage * STB + AB;
#pragma unroll
        for (int it = 0; it < 2; it++) {
            int idx = tid + it * 256;        // 512 chunks: 128 j x 4
            int j = idx >> 2, L = idx & 3;
            const char* g = (char*)g_coefTH
                + ((size_t)kt_ * NOUT + n0 + j) * 64 + L * 16;
            cp_async16(smem_u32(base + j * 64 + L * 16), g);
        }
    };

    float acc[2][8][4];
#pragma unroll
    for (int mt = 0; mt < 2; mt++)
#pragma unroll
        for (int nt = 0; nt < 8; nt++)
#pragma unroll
            for (int r = 0; r < 4; r++) acc[mt][nt][r] = 0.f;

    // prologue: fill STG-1 stages
#pragma unroll
    for (int s = 0; s < STG - 1; s++) {
        loadA(s, s); loadB(s, s);
        asm volatile("cp.async.commit_group;\n");
    }

    for (int kt = 0; kt < KT; kt++) {
        asm volatile("cp.async.wait_group %0;\n" :: "n"(STG - 2));
        __syncthreads();

        int ktn = kt + STG - 1;
        if (ktn < KT) {
            loadA(ktn % STG, ktn);
            loadB(ktn % STG, ktn);
        }
        asm volatile("cp.async.commit_group;\n");

        const char* As_ = smem + (kt % STG) * STB;
        const char* Bs_ = As_ + AB;

        // A fragments: 4 LDS.128 cover both k-steps of both 16-row tiles
        uint4 ua[2][2];
#pragma unroll
        for (int mt = 0; mt < 2; mt++) {
            int r = wm0 + mt * 16 + lr;
            ua[mt][0] = *(const uint4*)(As_ + r * 64 + lc * 16);
            ua[mt][1] = *(const uint4*)(As_ + (r + 8) * 64 + lc * 16);
        }
#pragma unroll
        for (int half = 0; half < 2; half++) {   // n-tiles 0-3 / 4-7
            uint4 ub[4];
#pragma unroll
            for (int q = 0; q < 4; q++) {
                int n = wn0 + (half * 4 + q) * 8 + lr;
                ub[q] = *(const uint4*)(Bs_ + n * 64 + lc * 16);
            }
#pragma unroll
            for (int mt = 0; mt < 2; mt++) {
#pragma unroll
                for (int q = 0; q < 4; q++) {
                    float* d = acc[mt][half * 4 + q];
                    // k-step 0: .x (kk 2lc,2lc+1), .y (kk 2lc+8,2lc+9)
                    mma_fp16(d, ua[mt][0].x, ua[mt][1].x, ua[mt][0].y, ua[mt][1].y,
                             ub[q].x, ub[q].y);
                    // k-step 1: .z, .w
                    mma_fp16(d, ua[mt][0].z, ua[mt][1].z, ua[mt][0].w, ua[mt][1].w,
                             ub[q].z, ub[q].w);
                }
            }
        }
    }

    // epilogue: fp32 stores
#pragma unroll
    for (int mt = 0; mt < 2; mt++) {
#pragma unroll
        for (int nt = 0; nt < 8; nt++) {
            int r = m0 + wm0 + mt * 16 + lr;
            int c = n0 + wn0 + nt * 8 + lc * 2;
            float2 lo = make_float2(acc[mt][nt][0], acc[mt][nt][1]);
            float2 hi = make_float2(acc[mt][nt][2], acc[mt][nt][3]);
            *(float2*)(out + (size_t)r * NOUT + c) = lo;
            *(float2*)(out + (size_t)(r + 8) * NOUT + c) = hi;
        }
    }
}

// ---------------------------------------------------------------------------
// launch
// ---------------------------------------------------------------------------
extern "C" void kernel_launch(void* const* d_in, const int* in_sizes, int n_in,
                              void* d_out, int out_size) {
    const float* x    = (const float*)d_in[0];   // [4096, 2048]
    const float* coef = (const float*)d_in[1];   // [2048, 2048, 8]
    const float* grid = (const float*)d_in[2];   // [8]
    float* out = (float*)d_out;                  // [4096, 2048]
    (void)in_sizes; (void)n_in; (void)out_size;

    basis_kernel<<<(BDIM * NIN) / 256, 256>>>(x, grid);
    coefT_kernel<<<(NBLK * NOUT) / 256, 256>>>(coef);

    cudaFuncSetAttribute(gemm_kernel,
                         cudaFuncAttributeMaxDynamicSharedMemorySize, GEMM_SMEM);
    dim3 g(NOUT / BN, BDIM / BM);                // (16, 32) = 512 CTAs
    gemm_kernel<<<g, 256, GEMM_SMEM>>>(out);
}

// round 12
// speedup vs baseline: 5.1268x; 1.0987x over previous
#include <cuda_runtime.h>
#include <cuda_fp16.h>
#include <cstdint>

// Problem shape (fixed by the reference)
#define BDIM 4096
#define NIN  2048
#define NOUT 2048
#define GS   8
#define KDIM (NIN * GS)     // 16384 contraction length
#define NBLK (KDIM / 32)    // 512 K-blocks of 32

// fp16 scratch, K-permuted within each 32-block:
//   value (g = i&3, k = 0..7) at byte (k>>1)*16 + (g>>1)*8 + (g&1)*4 + (k&1)*2
//   of the 64B block-row. One LDS.128 = full m16n8k16 fragment (both k-steps).
// g_basisH[b][blk][64B] (128 MB)  — blk contiguous => 128B covers 2 blocks
// g_coefTH[blk][j][64B] (64 MB)
__device__ __half g_basisH[(size_t)BDIM * KDIM];
__device__ __half g_coefTH[(size_t)NBLK * NOUT * 32];

// ---------------------------------------------------------------------------
// helpers
// ---------------------------------------------------------------------------
__device__ __forceinline__ uint32_t smem_u32(const void* p) {
    return (uint32_t)__cvta_generic_to_shared(p);
}
__device__ __forceinline__ void cp_async16(uint32_t s, const void* g) {
    asm volatile("cp.async.cg.shared.global [%0], [%1], 16;\n" :: "r"(s), "l"(g));
}
__device__ __forceinline__ void mma_fp16(float* d, uint32_t a0, uint32_t a1,
                                         uint32_t a2, uint32_t a3,
                                         uint32_t b0, uint32_t b1) {
    asm volatile(
        "mma.sync.aligned.m16n8k16.row.col.f32.f16.f16.f32 "
        "{%0,%1,%2,%3},{%4,%5,%6,%7},{%8,%9},{%0,%1,%2,%3};\n"
        : "+f"(d[0]), "+f"(d[1]), "+f"(d[2]), "+f"(d[3])
        : "r"(a0), "r"(a1), "r"(a2), "r"(a3), "r"(b0), "r"(b1));
}
__device__ __forceinline__ uint32_t h2u(__half2 h) {
    return *(uint32_t*)&h;
}

// ---------------------------------------------------------------------------
// Fused preprocessing: blocks [0, 32768) do basis, [32768, 36864) do coefT.
// Overlaps the two independent memory-bound passes in one launch.
// ---------------------------------------------------------------------------
#define BASIS_BLOCKS 32768
#define COEFT_BLOCKS 4096

__global__ void prep_kernel(const float* __restrict__ x,
                            const float* __restrict__ coef,
                            const float* __restrict__ grid) {
    if (blockIdx.x < BASIS_BLOCKS) {
        // basis: thread t owns (b,i); row = t>>2 (= b*NBLK + i>>2), g = t&3.
        int t = blockIdx.x * blockDim.x + threadIdx.x;
        float xv = x[t];
        float e[GS];
        float s = 0.f;
#pragma unroll
        for (int k = 0; k < GS; k++) {
            float d = xv - __ldg(grid + k);
            e[k] = __expf(-5.0f * d * d);
            s += e[k];
        }
        float inv = 1.0f / (s + 1e-8f);
        int g = t & 3;
        char* base = (char*)g_basisH + (size_t)(t >> 2) * 64
                   + (g >> 1) * 8 + (g & 1) * 4;
#pragma unroll
        for (int c = 0; c < 4; c++) {
            __half2 v = __floats2half2_rn(e[2 * c] * inv, e[2 * c + 1] * inv);
            *(__half2*)(base + c * 16) = v;
        }
    } else {
        // coefT: thread owns (blk, j); reads coef[4blk+g][j][0..7], writes 64B row.
        int idx = (blockIdx.x - BASIS_BLOCKS) * blockDim.x + threadIdx.x;
        int blk = idx >> 11, j = idx & (NOUT - 1);
        float v[4][8];
#pragma unroll
        for (int g = 0; g < 4; g++) {
            const float4* s =
                (const float4*)(coef + ((size_t)(blk * 4 + g) * NOUT + j) * GS);
            float4 lo = s[0], hi = s[1];
            v[g][0] = lo.x; v[g][1] = lo.y; v[g][2] = lo.z; v[g][3] = lo.w;
            v[g][4] = hi.x; v[g][5] = hi.y; v[g][6] = hi.z; v[g][7] = hi.w;
        }
        uint4* dst = (uint4*)((char*)g_coefTH + (size_t)idx * 64);
#pragma unroll
        for (int c = 0; c < 4; c++) {          // chunk c: k-pair (2c, 2c+1)
            uint4 o;
            o.x = h2u(__floats2half2_rn(v[0][2 * c], v[0][2 * c + 1]));
            o.y = h2u(__floats2half2_rn(v[1][2 * c], v[1][2 * c + 1]));
            o.z = h2u(__floats2half2_rn(v[2][2 * c], v[2][2 * c + 1]));
            o.w = h2u(__floats2half2_rn(v[3][2 * c], v[3][2 * c + 1]));
            dst[c] = o;
        }
    }
}

// ---------------------------------------------------------------------------
// GEMM: out = A @ B, fp16 HMMA m16n8k16 with fp32 accum.
// CTA tile 128x64, BK=64 (2 permuted 32-blocks per stage), 8 warps (4x2),
// warp tile 32x32, 4-stage cp.async pipeline, 96 KB smem -> 2 CTAs/SM.
// Grid = 1024 CTAs -> 6.92 CTAs/SM: wave-quantization loss ~1% (vs 14% @512).
// A rows: 128B (2 blocks), parity-XOR'd 64B halves => conflict-free LDS.128.
// B rows: 64B, naturally conflict-free (stride alternates halves).
// ---------------------------------------------------------------------------
#define BM 128
#define BN 64
#define STG 4
#define AB  (128 * 128)        // 16 KB A tile (128 rows x 128B)
#define BB  (2 * 64 * 64)      // 8 KB B tile (2 blocks x 64 rows x 64B)
#define STB (AB + BB)          // 24 KB per stage
#define GEMM_SMEM (STG * STB)  // 98304 bytes
#define KT2 (NBLK / 2)         // 256 outer iterations (64 K-elems each)

__global__ __launch_bounds__(256, 2)
void gemm_kernel(float* __restrict__ out) {
    extern __shared__ __align__(128) char smem[];

    const int tid  = threadIdx.x;
    const int lane = tid & 31;
    const int wid  = tid >> 5;
    const int m0 = blockIdx.y * BM;
    const int n0 = blockIdx.x * BN;
    const int wm0 = (wid >> 1) * 32;     // 4 warps along M
    const int wn0 = (wid & 1) * 32;      // 2 warps along N
    const int lr = lane >> 2;            // 0..7
    const int lc = lane & 3;             // 0..3

    auto loadA = [&](int stage, int s) {
        char* base = smem + stage * STB;
#pragma unroll
        for (int it = 0; it < 4; it++) {
            int idx = tid + it * 256;        // 1024 chunks: 128 rows x 8
            int row = idx >> 3, L = idx & 7;
            const char* g = (char*)g_basisH
                + ((size_t)(m0 + row) * NBLK + 2 * s) * 64 + L * 16;
            cp_async16(smem_u32(base + row * 128 + ((L * 16) ^ ((row & 1) * 64))), g);
        }
    };
    auto loadB = [&](int stage, int s) {
        char* base = smem + stage * STB + AB;
#pragma unroll
        for (int it = 0; it < 2; it++) {
            int idx = tid + it * 256;        // 512 chunks: 2 blocks x 64 j x 4
            int L = idx & 3, j = (idx >> 2) & 63, bb = idx >> 8;
            const char* g = (char*)g_coefTH
                + ((size_t)(2 * s + bb) * NOUT + n0 + j) * 64 + L * 16;
            cp_async16(smem_u32(base + bb * 4096 + j * 64 + L * 16), g);
        }
    };

    float acc[2][4][4];
#pragma unroll
    for (int mt = 0; mt < 2; mt++)
#pragma unroll
        for (int nt = 0; nt < 4; nt++)
#pragma unroll
            for (int r = 0; r < 4; r++) acc[mt][nt][r] = 0.f;

    // prologue: fill STG-1 stages
#pragma unroll
    for (int s = 0; s < STG - 1; s++) {
        loadA(s, s); loadB(s, s);
        asm volatile("cp.async.commit_group;\n");
    }

    for (int s = 0; s < KT2; s++) {
        asm volatile("cp.async.wait_group %0;\n" :: "n"(STG - 2));
        __syncthreads();

        int sn = s + STG - 1;
        if (sn < KT2) {
            loadA(sn % STG, sn);
            loadB(sn % STG, sn);
        }
        asm volatile("cp.async.commit_group;\n");

        const char* As_ = smem + (s % STG) * STB;
        const char* Bs_ = As_ + AB;

#pragma unroll
        for (int bb = 0; bb < 2; bb++) {     // the two 32-K blocks of this stage
            uint4 ua[2][2];
#pragma unroll
            for (int mt = 0; mt < 2; mt++) {
                int r = wm0 + mt * 16 + lr;
                int off = (bb * 64 + lc * 16);
                ua[mt][0] = *(const uint4*)(As_ + r * 128 + (off ^ ((r & 1) * 64)));
                ua[mt][1] = *(const uint4*)(As_ + (r + 8) * 128 + (off ^ (((r + 8) & 1) * 64)));
            }
            uint4 ub[4];
#pragma unroll
            for (int nt = 0; nt < 4; nt++) {
                int n = wn0 + nt * 8 + lr;
                ub[nt] = *(const uint4*)(Bs_ + bb * 4096 + n * 64 + lc * 16);
            }
#pragma unroll
            for (int mt = 0; mt < 2; mt++) {
#pragma unroll
                for (int nt = 0; nt < 4; nt++) {
                    float* d = acc[mt][nt];
                    mma_fp16(d, ua[mt][0].x, ua[mt][1].x, ua[mt][0].y, ua[mt][1].y,
                             ub[nt].x, ub[nt].y);
                    mma_fp16(d, ua[mt][0].z, ua[mt][1].z, ua[mt][0].w, ua[mt][1].w,
                             ub[nt].z, ub[nt].w);
                }
            }
        }
    }

    // epilogue: fp32 stores
#pragma unroll
    for (int mt = 0; mt < 2; mt++) {
#pragma unroll
        for (int nt = 0; nt < 4; nt++) {
            int r = m0 + wm0 + mt * 16 + lr;
            int c = n0 + wn0 + nt * 8 + lc * 2;
            float2 lo = make_float2(acc[mt][nt][0], acc[mt][nt][1]);
            float2 hi = make_float2(acc[mt][nt][2], acc[mt][nt][3]);
            *(float2*)(out + (size_t)r * NOUT + c) = lo;
            *(float2*)(out + (size_t)(r + 8) * NOUT + c) = hi;
        }
    }
}

// ---------------------------------------------------------------------------
// launch
// ---------------------------------------------------------------------------
extern "C" void kernel_launch(void* const* d_in, const int* in_sizes, int n_in,
                              void* d_out, int out_size) {
    const float* x    = (const float*)d_in[0];   // [4096, 2048]
    const float* coef = (const float*)d_in[1];   // [2048, 2048, 8]
    const float* grid = (const float*)d_in[2];   // [8]
    float* out = (float*)d_out;                  // [4096, 2048]
    (void)in_sizes; (void)n_in; (void)out_size;

    prep_kernel<<<BASIS_BLOCKS + COEFT_BLOCKS, 256>>>(x, coef, grid);

    cudaFuncSetAttribute(gemm_kernel,
                         cudaFuncAttributeMaxDynamicSharedMemorySize, GEMM_SMEM);
    dim3 g(NOUT / BN, BDIM / BM);                // (32, 32) = 1024 CTAs
    gemm_kernel<<<g, 256, GEMM_SMEM>>>(out);
}

// round 14
// speedup vs baseline: 5.3963x; 1.0526x over previous
#include <cuda_runtime.h>
#include <cuda_fp16.h>
#include <cstdint>

// Problem shape (fixed by the reference)
#define BDIM 4096
#define NIN  2048
#define NOUT 2048
#define GS   8
#define KDIM (NIN * GS)     // 16384 contraction length
#define NBLK (KDIM / 32)    // 512 K-blocks of 32

// fp16 scratch, K-permuted within each 32-block:
//   value (g = i&3, k = 0..7) at byte (k>>1)*16 + (g>>1)*8 + (g&1)*4 + (k&1)*2
//   of the 64B block-row. One LDS.128 = full m16n8k16 fragment (both k-steps).
__device__ __half g_basisH[(size_t)BDIM * KDIM];
__device__ __half g_coefTH[(size_t)NBLK * NOUT * 32];

// ---------------------------------------------------------------------------
// helpers
// ---------------------------------------------------------------------------
__device__ __forceinline__ uint32_t smem_u32(const void* p) {
    return (uint32_t)__cvta_generic_to_shared(p);
}
__device__ __forceinline__ void cp_async16(uint32_t s, const void* g) {
    asm volatile("cp.async.cg.shared.global [%0], [%1], 16;\n" :: "r"(s), "l"(g));
}
__device__ __forceinline__ void mma_fp16(float* d, uint32_t a0, uint32_t a1,
                                         uint32_t a2, uint32_t a3,
                                         uint32_t b0, uint32_t b1) {
    asm volatile(
        "mma.sync.aligned.m16n8k16.row.col.f32.f16.f16.f32 "
        "{%0,%1,%2,%3},{%4,%5,%6,%7},{%8,%9},{%0,%1,%2,%3};\n"
        : "+f"(d[0]), "+f"(d[1]), "+f"(d[2]), "+f"(d[3])
        : "r"(a0), "r"(a1), "r"(a2), "r"(a3), "r"(b0), "r"(b1));
}
__device__ __forceinline__ uint32_t h2u(__half2 h) {
    return *(uint32_t*)&h;
}

// ---------------------------------------------------------------------------
// Fused preprocessing: blocks [0, 32768) basis, [32768, 36864) coefT.
// ---------------------------------------------------------------------------
#define BASIS_BLOCKS 32768
#define COEFT_BLOCKS 4096

__global__ void prep_kernel(const float* __restrict__ x,
                            const float* __restrict__ coef,
                            const float* __restrict__ grid) {
    if (blockIdx.x < BASIS_BLOCKS) {
        int t = blockIdx.x * blockDim.x + threadIdx.x;
        float xv = x[t];
        float e[GS];
        float s = 0.f;
#pragma unroll
        for (int k = 0; k < GS; k++) {
            float d = xv - __ldg(grid + k);
            e[k] = __expf(-5.0f * d * d);
            s += e[k];
        }
        float inv = 1.0f / (s + 1e-8f);
        int g = t & 3;
        char* base = (char*)g_basisH + (size_t)(t >> 2) * 64
                   + (g >> 1) * 8 + (g & 1) * 4;
#pragma unroll
        for (int c = 0; c < 4; c++) {
            __half2 v = __floats2half2_rn(e[2 * c] * inv, e[2 * c + 1] * inv);
            *(__half2*)(base + c * 16) = v;
        }
    } else {
        int idx = (blockIdx.x - BASIS_BLOCKS) * blockDim.x + threadIdx.x;
        int blk = idx >> 11, j = idx & (NOUT - 1);
        float v[4][8];
#pragma unroll
        for (int g = 0; g < 4; g++) {
            const float4* s =
                (const float4*)(coef + ((size_t)(blk * 4 + g) * NOUT + j) * GS);
            float4 lo = s[0], hi = s[1];
            v[g][0] = lo.x; v[g][1] = lo.y; v[g][2] = lo.z; v[g][3] = lo.w;
            v[g][4] = hi.x; v[g][5] = hi.y; v[g][6] = hi.z; v[g][7] = hi.w;
        }
        uint4* dst = (uint4*)((char*)g_coefTH + (size_t)idx * 64);
#pragma unroll
        for (int c = 0; c < 4; c++) {
            uint4 o;
            o.x = h2u(__floats2half2_rn(v[0][2 * c], v[0][2 * c + 1]));
            o.y = h2u(__floats2half2_rn(v[1][2 * c], v[1][2 * c + 1]));
            o.z = h2u(__floats2half2_rn(v[2][2 * c], v[2][2 * c + 1]));
            o.w = h2u(__floats2half2_rn(v[3][2 * c], v[3][2 * c + 1]));
            dst[c] = o;
        }
    }
}

// ---------------------------------------------------------------------------
// GEMM: out = A @ B, fp16 HMMA m16n8k16, fp32 accum.
// CTA tile 128x64, BK=64. 8 warps = 2(M) x 2(N) x 2(K-split):
//   warp tile 64x32; K-warp kw handles block bb=kw of each stage.
// LDS/CTA-iter: 48 KB (vs 64 KB for 32x32 warps) -> crossbar ~ HMMA balanced.
// 4-stage cp.async pipeline, 96 KB smem, 2 CTAs/SM, grid 1024 (~1% wave loss).
// Epilogue: kw=1 warps push partials through smem; kw=0 adds + stores.
// ---------------------------------------------------------------------------
#define BM 128
#define BN 64
#define STG 4
#define AB  (128 * 128)        // 16 KB A tile (128 rows x 128B = 2 K-blocks)
#define BB  (2 * 64 * 64)      // 8 KB B tile (2 blocks x 64 j x 64B)
#define STB (AB + BB)          // 24 KB per stage
#define GEMM_SMEM (STG * STB)  // 98304 bytes
#define KT2 (NBLK / 2)         // 256 outer iterations (64 K-elems each)

__global__ __launch_bounds__(256, 2)
void gemm_kernel(float* __restrict__ out) {
    extern __shared__ __align__(128) char smem[];

    const int tid  = threadIdx.x;
    const int lane = tid & 31;
    const int wid  = tid >> 5;
    const int m0 = blockIdx.y * BM;
    const int n0 = blockIdx.x * BN;
    const int wm_i = (wid >> 2) & 1;     // 2 warps along M (64 rows each)
    const int wn_i = (wid >> 1) & 1;     // 2 warps along N (32 cols each)
    const int kw   = wid & 1;            // K-split: this warp's 32-K block
    const int lr = lane >> 2;            // 0..7
    const int lc = lane & 3;             // 0..3

    auto loadA = [&](int stage, int s) {
        char* base = smem + stage * STB;
#pragma unroll
        for (int it = 0; it < 4; it++) {
            int idx = tid + it * 256;        // 1024 chunks: 128 rows x 8
            int row = idx >> 3, L = idx & 7;
            const char* g = (char*)g_basisH
                + ((size_t)(m0 + row) * NBLK + 2 * s) * 64 + L * 16;
            cp_async16(smem_u32(base + row * 128 + ((L * 16) ^ ((row & 1) * 64))), g);
        }
    };
    auto loadB = [&](int stage, int s) {
        char* base = smem + stage * STB + AB;
#pragma unroll
        for (int it = 0; it < 2; it++) {
            int idx = tid + it * 256;        // 512 chunks: 2 blocks x 64 j x 4
            int L = idx & 3, j = (idx >> 2) & 63, bb = idx >> 8;
            const char* g = (char*)g_coefTH
                + ((size_t)(2 * s + bb) * NOUT + n0 + j) * 64 + L * 16;
            cp_async16(smem_u32(base + bb * 4096 + j * 64 + L * 16), g);
        }
    };

    float acc[4][4][4];                  // [mt][nt][frag]
#pragma unroll
    for (int mt = 0; mt < 4; mt++)
#pragma unroll
        for (int nt = 0; nt < 4; nt++)
#pragma unroll
            for (int r = 0; r < 4; r++) acc[mt][nt][r] = 0.f;

    // prologue
#pragma unroll
    for (int s = 0; s < STG - 1; s++) {
        loadA(s, s); loadB(s, s);
        asm volatile("cp.async.commit_group;\n");
    }

    const int aoff = kw * 64 + lc * 16;  // this warp's K-block chunk offset

    for (int s = 0; s < KT2; s++) {
        asm volatile("cp.async.wait_group %0;\n" :: "n"(STG - 2));
        __syncthreads();

        int sn = s + STG - 1;
        if (sn < KT2) {
            loadA(sn % STG, sn);
            loadB(sn % STG, sn);
        }
        asm volatile("cp.async.commit_group;\n");

        const char* As_ = smem + (s % STG) * STB;
        const char* Bs_ = As_ + AB;

        // B fragments for this warp's K-block: 4 LDS.128
        uint4 ub[4];
#pragma unroll
        for (int nt = 0; nt < 4; nt++) {
            int n = wn_i * 32 + nt * 8 + lr;
            ub[nt] = *(const uint4*)(Bs_ + kw * 4096 + n * 64 + lc * 16);
        }
        // A fragments in two mt-halves to bound live registers
#pragma unroll
        for (int hm = 0; hm < 2; hm++) {
            uint4 ua[2][2];
#pragma unroll
            for (int m2 = 0; m2 < 2; m2++) {
                int r = wm_i * 64 + (hm * 2 + m2) * 16 + lr;
                ua[m2][0] = *(const uint4*)(As_ + r * 128 + (aoff ^ ((r & 1) * 64)));
                ua[m2][1] = *(const uint4*)(As_ + (r + 8) * 128 + (aoff ^ (((r + 8) & 1) * 64)));
            }
#pragma unroll
            for (int m2 = 0; m2 < 2; m2++) {
#pragma unroll
                for (int nt = 0; nt < 4; nt++) {
                    float* d = acc[hm * 2 + m2][nt];
                    mma_fp16(d, ua[m2][0].x, ua[m2][1].x, ua[m2][0].y, ua[m2][1].y,
                             ub[nt].x, ub[nt].y);
                    mma_fp16(d, ua[m2][0].z, ua[m2][1].z, ua[m2][0].w, ua[m2][1].w,
                             ub[nt].z, ub[nt].w);
                }
            }
        }
    }

    // ---- K-split reduction + store ----
    __syncthreads();                     // all fragment reads done; smem reusable
    float* red = (float*)smem;
    const int pos = (wm_i * 2 + wn_i) * 2048;   // 64x32 fp32 region per spatial pos

    if (kw == 1) {
#pragma unroll
        for (int mt = 0; mt < 4; mt++) {
#pragma unroll
            for (int nt = 0; nt < 4; nt++) {
                int lrow = mt * 16 + lr, col = nt * 8 + lc * 2;
                *(float2*)(red + pos + lrow * 32 + col) =
                    make_float2(acc[mt][nt][0], acc[mt][nt][1]);
                *(float2*)(red + pos + (lrow + 8) * 32 + col) =
                    make_float2(acc[mt][nt][2], acc[mt][nt][3]);
            }
        }
    }
    __syncthreads();
    if (kw == 0) {
#pragma unroll
        for (int mt = 0; mt < 4; mt++) {
#pragma unroll
            for (int nt = 0; nt < 4; nt++) {
                int lrow = mt * 16 + lr, col = nt * 8 + lc * 2;
                float2 p0 = *(float2*)(red + pos + lrow * 32 + col);
                float2 p1 = *(float2*)(red + pos + (lrow + 8) * 32 + col);
                int r = m0 + wm_i * 64 + mt * 16 + lr;
                int c = n0 + wn_i * 32 + nt * 8 + lc * 2;
                *(float2*)(out + (size_t)r * NOUT + c) =
                    make_float2(acc[mt][nt][0] + p0.x, acc[mt][nt][1] + p0.y);
                *(float2*)(out + (size_t)(r + 8) * NOUT + c) =
                    make_float2(acc[mt][nt][2] + p1.x, acc[mt][nt][3] + p1.y);
            }
        }
    }
}

// ---------------------------------------------------------------------------
// launch
// ---------------------------------------------------------------------------
extern "C" void kernel_launch(void* const* d_in, const int* in_sizes, int n_in,
                              void* d_out, int out_size) {
    const float* x    = (const float*)d_in[0];   // [4096, 2048]
    const float* coef = (const float*)d_in[1];   // [2048, 2048, 8]
    const float* grid = (const float*)d_in[2];   // [8]
    float* out = (float*)d_out;                  // [4096, 2048]
    (void)in_sizes; (void)n_in; (void)out_size;

    prep_kernel<<<BASIS_BLOCKS + COEFT_BLOCKS, 256>>>(x, coef, grid);

    cudaFuncSetAttribute(gemm_kernel,
                         cudaFuncAttributeMaxDynamicSharedMemorySize, GEMM_SMEM);
    dim3 g(NOUT / BN, BDIM / BM);                // (32, 32) = 1024 CTAs
    gemm_kernel<<<g, 256, GEMM_SMEM>>>(out);
}